// round 1
// baseline (speedup 1.0000x reference)
#include <cuda_runtime.h>
#include <math.h>

#define BB 4
#define CC 64
#define HH 128
#define WW 128
#define NT 256

// Scratch buffers (allocation-free: __device__ globals)
__device__ float d_buf_o[BB*CC*HH*WW];
__device__ float d_buf_r[BB*CC*HH*WW];   // resblock temp / MFE branch accumulator
__device__ float d_buf_t[BB*CC*HH*WW];   // MFE branch first-conv temp
__device__ float d_stats[2*BB*CC];       // [0:256) max, [256:512) avg
__device__ float d_cg[BB*CC];

struct Epi {
    const float* bias;   // [64] slice (per-oc), may be null
    const float* res;    // residual add (resblock), may be null
    const float* acc;    // branch accumulator add, may be null
    const float* cg;     // per (b,oc) output scale, may be null
    const float* map;    // final: [B,H,W], may be null
    const float* xres;   // final: original x, used iff map set
    float* out;
    int act;             // 0 none, 1 relu, 2 lrelu(0.01)
};

// Direct conv, pad = K/2, stride 1. Block: 32x32 spatial tile x 8 output channels.
// 256 threads: tx = tid&7 -> 4 consecutive cols, ty = tid>>3 -> row.
template<int K>
__global__ __launch_bounds__(NT) void conv_kernel(
    const float* __restrict__ in,      // [B,C,H,W] (batch base applied inside)
    const float* __restrict__ w,       // [64,64,K,K] slice
    float wscale,
    const float* __restrict__ cond,    // [B*64] per-(b,ic) input scale or null
    Epi e)
{
    constexpr int PAD = K/2;
    constexpr int TH = 32, TW = 32, OCB = 8;
    constexpr int IHS = TH + 2*PAD, IWS = TW + 2*PAD;
    constexpr int STR = (IWS % 2 == 0) ? IWS + 1 : IWS;  // odd -> conflict-free

    __shared__ float s_in[IHS*STR];
    __shared__ float s_w[OCB*K*K];

    const int tid = threadIdx.x;
    const int tx = tid & 7;        // col group
    const int ty = tid >> 3;       // row 0..31
    const int bx = blockIdx.x, by = blockIdx.y;
    const int b  = blockIdx.z >> 3;
    const int ocg = blockIdx.z & 7;
    const int gy0 = by*TH, gx0 = bx*TW;

    float acc[OCB][4];
    #pragma unroll
    for (int o = 0; o < OCB; o++)
        #pragma unroll
        for (int c = 0; c < 4; c++) acc[o][c] = 0.f;

    const float* inb = in + (size_t)b*CC*HH*WW;

    for (int ic = 0; ic < CC; ic++) {
        const float cs = cond ? cond[b*CC + ic] : 1.f;
        const float* inc = inb + (size_t)ic*HH*WW;
        // load padded input tile
        for (int idx = tid; idx < IHS*IWS; idx += NT) {
            const int r = idx / IWS, c = idx % IWS;
            const int gh = gy0 + r - PAD, gw = gx0 + c - PAD;
            float v = 0.f;
            if (gh >= 0 && gh < HH && gw >= 0 && gw < WW)
                v = inc[gh*WW + gw] * cs;
            s_in[r*STR + c] = v;
        }
        // load this ic's weights for 8 ocs
        if (tid < OCB*K*K) {
            const int o = tid / (K*K), k = tid % (K*K);
            s_w[tid] = w[(((size_t)(ocg*OCB + o))*CC + ic)*(K*K) + k] * wscale;
        }
        __syncthreads();

        // pull this thread's input window into registers
        float r_in[K][K+3];
        #pragma unroll
        for (int kh = 0; kh < K; kh++)
            #pragma unroll
            for (int cc = 0; cc < K+3; cc++)
                r_in[kh][cc] = s_in[(ty + kh)*STR + 4*tx + cc];

        #pragma unroll
        for (int o = 0; o < OCB; o++) {
            #pragma unroll
            for (int kh = 0; kh < K; kh++)
                #pragma unroll
                for (int kw = 0; kw < K; kw++) {
                    const float wv = s_w[o*K*K + kh*K + kw];
                    #pragma unroll
                    for (int c = 0; c < 4; c++)
                        acc[o][c] = fmaf(r_in[kh][kw + c], wv, acc[o][c]);
                }
        }
        __syncthreads();
    }

    // epilogue
    const int oh = gy0 + ty;
    #pragma unroll
    for (int o = 0; o < OCB; o++) {
        const int oc = ocg*OCB + o;
        const float bv  = e.bias ? e.bias[oc] : 0.f;
        const float cgv = e.cg ? e.cg[b*CC + oc] : 1.f;
        #pragma unroll
        for (int c = 0; c < 4; c++) {
            const int ow = gx0 + 4*tx + c;
            const size_t idx = (((size_t)b*CC + oc)*HH + oh)*WW + ow;
            float v = acc[o][c] + bv;
            if (e.act == 1)      v = fmaxf(v, 0.f);
            else if (e.act == 2) v = (v > 0.f) ? v : 0.01f*v;
            if (e.res) v += e.res[idx];
            if (e.acc) v += e.acc[idx];
            v *= cgv;
            if (e.map) v = v * e.map[(size_t)b*HH*WW + oh*WW + ow] + e.xres[idx];
            e.out[idx] = v;
        }
    }
}

// Per-(b,c) max + mean over HxW
__global__ __launch_bounds__(NT) void stats_kernel(const float* __restrict__ in,
                                                   float* __restrict__ st)
{
    const int bc = blockIdx.x;                // 0..255
    const float* p = in + (size_t)bc*HH*WW;
    const int tid = threadIdx.x;
    float mx = -3.4e38f, sm = 0.f;
    for (int i = tid; i < HH*WW; i += NT) {
        const float v = p[i];
        mx = fmaxf(mx, v);
        sm += v;
    }
    __shared__ float smx[NT], ssm[NT];
    smx[tid] = mx; ssm[tid] = sm;
    __syncthreads();
    for (int s = NT/2; s > 0; s >>= 1) {
        if (tid < s) {
            smx[tid] = fmaxf(smx[tid], smx[tid+s]);
            ssm[tid] += ssm[tid+s];
        }
        __syncthreads();
    }
    if (tid == 0) {
        st[bc] = smx[0];
        st[BB*CC + bc] = ssm[0] * (1.f/(HH*WW));
    }
}

// Channel attention -> Cg  (one block, 256 threads, thread = (b,c))
__global__ void cg_kernel(const float* __restrict__ st,
                          const float* __restrict__ cw1,  // [4,64]
                          const float* __restrict__ cw2,  // [64,4]
                          const float* __restrict__ fw,   // [2]
                          const float* __restrict__ fb,   // [2]
                          float* __restrict__ cg)
{
    const int t = threadIdx.x;
    const int b = t >> 6, c = t & 63;
    float se = 0.f;
    #pragma unroll
    for (int h = 0; h < 4; h++) {
        float hm = 0.f, ha = 0.f;
        for (int i = 0; i < CC; i++) {
            const float wv = cw1[h*CC + i];
            hm += wv * st[b*CC + i];
            ha += wv * st[BB*CC + b*CC + i];
        }
        hm = fmaxf(hm, 0.f);
        ha = fmaxf(ha, 0.f);
        se += cw2[c*4 + h] * (hm + ha);
    }
    const float xll = 1.f / (1.f + expf(-se));
    cg[t] = fw[1]*(fw[0]*xll + fb[0]) + fb[1];
}

static Epi mkEpi(const float* bias, int act, float* out) {
    Epi e;
    e.bias = bias; e.res = nullptr; e.acc = nullptr; e.cg = nullptr;
    e.map = nullptr; e.xres = nullptr; e.out = out; e.act = act;
    return e;
}

extern "C" void kernel_launch(void* const* d_in, const int* in_sizes, int n_in,
                              void* d_out, int out_size)
{
    const float* x    = (const float*)d_in[0];
    const float* cf1  = (const float*)d_in[1];  // [5,2,B,1,C,1,1]
    const float* cf2  = (const float*)d_in[2];  // [4,2,B,1,C,1,1]
    const float* map_ = (const float*)d_in[3];  // [B,1,H,W]
    const float* resw = (const float*)d_in[4];  // [9,2,C,C,3,3]
    const float* resb = (const float*)d_in[5];  // [9,2,C]
    const float* mw1  = (const float*)d_in[6];  // [5,2,C,C,1,1]
    const float* mb1  = (const float*)d_in[7];
    const float* mw3  = (const float*)d_in[8];  // [5,2,C,C,3,3]
    const float* mb3  = (const float*)d_in[9];
    const float* mw5  = (const float*)d_in[10]; // [5,2,C,C,5,5]
    const float* mb5  = (const float*)d_in[11];
    const float* caw1 = (const float*)d_in[12]; // [5,4,64]
    const float* caw2 = (const float*)d_in[13]; // [5,64,4]
    const float* fcw  = (const float*)d_in[14]; // [5,2]
    const float* fcb  = (const float*)d_in[15]; // [5,2]
    float* out = (float*)d_out;

    float *bo, *br, *bt, *bst, *bcg;
    cudaGetSymbolAddress((void**)&bo,  d_buf_o);
    cudaGetSymbolAddress((void**)&br,  d_buf_r);
    cudaGetSymbolAddress((void**)&bt,  d_buf_t);
    cudaGetSymbolAddress((void**)&bst, d_stats);
    cudaGetSymbolAddress((void**)&bcg, d_cg);

    const float SCALE = 1.0f / 24.0f;   // 1/sqrt(64*9)
    const dim3 grid(WW/32, HH/32, BB*8);
    const dim3 blk(NT);

    const int mfe_after[9] = {-1, 0, -1, 1, -1, 2, -1, 3, 4};
    const float* cur = x;

    for (int i = 0; i < 9; i++) {
        // ---- resblock i ----
        const float* c0 = (i < 5) ? cf1 + (size_t)(i*2+0)*BB*CC
                                  : cf2 + (size_t)((i-5)*2+0)*BB*CC;
        const float* c1 = c0 + BB*CC;
        const float* w0 = resw + (size_t)(i*2+0)*CC*CC*9;
        const float* w1 = resw + (size_t)(i*2+1)*CC*CC*9;

        Epi e1 = mkEpi(resb + (size_t)(i*2+0)*CC, /*relu*/1, br);
        conv_kernel<3><<<grid, blk>>>(cur, w0, SCALE, c0, e1);

        Epi e2 = mkEpi(resb + (size_t)(i*2+1)*CC, /*none*/0, bo);
        e2.res = cur;                                   // + x residual
        conv_kernel<3><<<grid, blk>>>(br, w1, SCALE, c1, e2);
        cur = bo;

        // ---- MFE j (if any) ----
        const int j = mfe_after[i];
        if (j >= 0) {
            stats_kernel<<<BB*CC, blk>>>(cur, bst);
            cg_kernel<<<1, blk>>>(bst, caw1 + (size_t)j*4*CC, caw2 + (size_t)j*CC*4,
                                  fcw + j*2, fcb + j*2, bcg);

            // branch 1x1: cur -> bt (lrelu) -> br (init acc)
            Epi a1 = mkEpi(mb1 + (size_t)(j*2+0)*CC, 2, bt);
            conv_kernel<1><<<grid, blk>>>(cur, mw1 + (size_t)(j*2+0)*CC*CC, 1.f, nullptr, a1);
            Epi b1 = mkEpi(mb1 + (size_t)(j*2+1)*CC, 0, br);
            conv_kernel<1><<<grid, blk>>>(bt, mw1 + (size_t)(j*2+1)*CC*CC, 1.f, nullptr, b1);

            // branch 3x3: cur -> bt (lrelu) -> br (+= acc, in place)
            Epi a3 = mkEpi(mb3 + (size_t)(j*2+0)*CC, 2, bt);
            conv_kernel<3><<<grid, blk>>>(cur, mw3 + (size_t)(j*2+0)*CC*CC*9, 1.f, nullptr, a3);
            Epi b3 = mkEpi(mb3 + (size_t)(j*2+1)*CC, 0, br);
            b3.acc = br;
            conv_kernel<3><<<grid, blk>>>(bt, mw3 + (size_t)(j*2+1)*CC*CC*9, 1.f, nullptr, b3);

            // branch 5x5: cur -> bt (lrelu) -> final (Cg*(acc+this) [, *map + x])
            Epi a5 = mkEpi(mb5 + (size_t)(j*2+0)*CC, 2, bt);
            conv_kernel<5><<<grid, blk>>>(cur, mw5 + (size_t)(j*2+0)*CC*CC*25, 1.f, nullptr, a5);

            Epi b5 = mkEpi(mb5 + (size_t)(j*2+1)*CC, 0, (j == 4) ? out : bo);
            b5.acc = br;
            b5.cg  = bcg;
            if (j == 4) { b5.map = map_; b5.xres = x; }
            conv_kernel<5><<<grid, blk>>>(bt, mw5 + (size_t)(j*2+1)*CC*CC*25, 1.f, nullptr, b5);
            cur = bo;
        }
    }
}